// round 4
// baseline (speedup 1.0000x reference)
#include <cuda_runtime.h>
#include <cstdint>

// Problem constants
#define N_ROWS 8192
#define D_COLS 1024
#define D4     256                      // float4 columns per row
#define NBLK1  2048                     // kernel1 blocks
#define ROWS_PER_BLK 4                  // 8192 / 2048
#define ROW_BYTES 4096                  // 1024 floats
#define N_STAGES 4                      // one row (src+tgt) per stage

// Scratch (device globals; no allocation):
__device__ float4 g_partial[NBLK1 * D4];    // [2048][1024] floats = 8 MB
__device__ float  g_partial2[32 * D_COLS];  // 128 KB

__device__ __forceinline__ uint32_t smem_u32(const void* p) {
    return (uint32_t)__cvta_generic_to_shared(p);
}

__device__ __forceinline__ void mbar_init(uint32_t mb, int count) {
    asm volatile("mbarrier.init.shared::cta.b64 [%0], %1;"
                 :: "r"(mb), "r"(count) : "memory");
}

__device__ __forceinline__ void mbar_expect_tx(uint32_t mb, uint32_t bytes) {
    asm volatile("mbarrier.arrive.expect_tx.shared::cta.b64 _, [%0], %1;"
                 :: "r"(mb), "r"(bytes) : "memory");
}

__device__ __forceinline__ void bulk_g2s(uint32_t dst, const void* src,
                                         uint32_t bytes, uint32_t mb) {
    asm volatile(
        "cp.async.bulk.shared::cta.global.mbarrier::complete_tx::bytes "
        "[%0], [%1], %2, [%3];"
        :: "r"(dst), "l"(src), "r"(bytes), "r"(mb) : "memory");
}

__device__ __forceinline__ void mbar_wait_parity0(uint32_t mb) {
    asm volatile(
        "{\n\t"
        ".reg .pred p;\n\t"
        "WAIT_%=:\n\t"
        "mbarrier.try_wait.parity.acquire.cta.shared::cta.b64 p, [%0], 0, 0x989680;\n\t"
        "@p bra DONE_%=;\n\t"
        "bra WAIT_%=;\n\t"
        "DONE_%=:\n\t"
        "}"
        :: "r"(mb) : "memory");
}

// ---------------------------------------------------------------------------
// Kernel 1: TMA-fed streaming column-sum of (source - target).
// 2048 blocks x 256 threads. Block handles 4 consecutive rows; each row is
// one single-shot stage: bulk-copy src row (4KB) + tgt row (4KB) into smem,
// then all threads reduce their float4 column group from smem.
// ---------------------------------------------------------------------------
__global__ __launch_bounds__(256)
void mmd_colsum_tma(const float* __restrict__ src,
                    const float* __restrict__ tgt) {
    // [stage][0..255]=src row, [256..511]=tgt row
    __shared__ alignas(16) float4 buf[N_STAGES][512];
    __shared__ alignas(8)  unsigned long long mbar[N_STAGES];

    const int t   = threadIdx.x;
    const int blk = blockIdx.x;

    if (t == 0) {
#pragma unroll
        for (int s = 0; s < N_STAGES; s++)
            mbar_init(smem_u32(&mbar[s]), 1);
    }
    __syncthreads();

    if (t == 0) {
        const char* srcb = (const char*)src + (size_t)blk * ROWS_PER_BLK * ROW_BYTES;
        const char* tgtb = (const char*)tgt + (size_t)blk * ROWS_PER_BLK * ROW_BYTES;
#pragma unroll
        for (int s = 0; s < N_STAGES; s++) {
            uint32_t mb = smem_u32(&mbar[s]);
            mbar_expect_tx(mb, 2 * ROW_BYTES);
            bulk_g2s(smem_u32(&buf[s][0]),   srcb + (size_t)s * ROW_BYTES, ROW_BYTES, mb);
            bulk_g2s(smem_u32(&buf[s][256]), tgtb + (size_t)s * ROW_BYTES, ROW_BYTES, mb);
        }
    }

    float ax = 0.f, ay = 0.f, az = 0.f, aw = 0.f;
#pragma unroll
    for (int s = 0; s < N_STAGES; s++) {
        mbar_wait_parity0(smem_u32(&mbar[s]));
        float4 sv = buf[s][t];
        float4 tv = buf[s][t + 256];
        ax += sv.x - tv.x;
        ay += sv.y - tv.y;
        az += sv.z - tv.z;
        aw += sv.w - tv.w;
    }

    float4 acc; acc.x = ax; acc.y = ay; acc.z = az; acc.w = aw;
    g_partial[blk * D4 + t] = acc;
}

// ---------------------------------------------------------------------------
// Kernel 2: reduce 2048 partial rows -> 32 partial rows.
// 32 blocks x 1024 threads; block b sums partial rows [b*64, b*64+64).
// ---------------------------------------------------------------------------
__global__ __launch_bounds__(1024)
void mmd_reduce_kernel() {
    const int d = threadIdx.x;               // column 0..1023
    const int b = blockIdx.x;                // 0..31
    const float* p = reinterpret_cast<const float*>(g_partial);

    float s = 0.f;
#pragma unroll
    for (int r = 0; r < 64; r++) {
        s += p[(long)(b * 64 + r) * D_COLS + d];
    }
    g_partial2[b * D_COLS + d] = s;
}

// ---------------------------------------------------------------------------
// Kernel 3: finish column sums, square, block-reduce, scale, write scalar.
// ---------------------------------------------------------------------------
__global__ __launch_bounds__(1024)
void mmd_final_kernel(float* __restrict__ out) {
    const int d = threadIdx.x;               // column 0..1023

    float s = 0.f;
#pragma unroll
    for (int r = 0; r < 32; r++) {
        s += g_partial2[r * D_COLS + d];
    }
    float sq = s * s;

    __shared__ float red[1024];
    red[d] = sq;
    __syncthreads();
#pragma unroll
    for (int off = 512; off > 0; off >>= 1) {
        if (d < off) red[d] += red[d + off];
        __syncthreads();
    }
    if (d == 0)
        out[0] = red[0] * (1.0f / ((float)N_ROWS * (float)N_ROWS));
}

// ---------------------------------------------------------------------------
extern "C" void kernel_launch(void* const* d_in, const int* in_sizes, int n_in,
                              void* d_out, int out_size) {
    const float* src = (const float*)d_in[0];
    const float* tgt = (const float*)d_in[1];
    float* out = (float*)d_out;

    mmd_colsum_tma<<<NBLK1, 256>>>(src, tgt);
    mmd_reduce_kernel<<<32, 1024>>>();
    mmd_final_kernel<<<1, 1024>>>(out);
}

// round 6
// speedup vs baseline: 1.1373x; 1.1373x over previous
#include <cuda_runtime.h>
#include <cstdint>

// Problem constants
#define N_ROWS 8192
#define D_COLS 1024
#define NBLK1  512                     // kernel1 blocks
#define ROWS_PER_BLK 16                // 8192 / 512
#define GROUPS_PER_BLK 2048            // 16 rows * 128 float8-groups
// partials: [512][2048] floats = 4 MB; flat index mod 1024 == column
__device__ float  g_partial[NBLK1 * GROUPS_PER_BLK];
__device__ float  g_partial2[32 * D_COLS];  // 128 KB

// 256-bit input load, L2 evict_last (try to keep inputs resident)
__device__ __forceinline__ void ldg256_keep(const float* p,
                                            float4& a, float4& b) {
    uint32_t r0, r1, r2, r3, r4, r5, r6, r7;
    asm("ld.global.nc.L2::evict_last.v8.b32 "
        "{%0,%1,%2,%3,%4,%5,%6,%7}, [%8];"
        : "=r"(r0), "=r"(r1), "=r"(r2), "=r"(r3),
          "=r"(r4), "=r"(r5), "=r"(r6), "=r"(r7)
        : "l"(p));
    a.x = __uint_as_float(r0); a.y = __uint_as_float(r1);
    a.z = __uint_as_float(r2); a.w = __uint_as_float(r3);
    b.x = __uint_as_float(r4); b.y = __uint_as_float(r5);
    b.z = __uint_as_float(r6); b.w = __uint_as_float(r7);
}

// Streaming partial store (evict_first)
__device__ __forceinline__ void stg_stream4(float* p, float4 v) {
    asm volatile("st.global.cs.v4.f32 [%0], {%1,%2,%3,%4};"
                 :: "l"(p), "f"(v.x), "f"(v.y), "f"(v.z), "f"(v.w)
                 : "memory");
}

// ---------------------------------------------------------------------------
// Kernel 1: streaming column-sum of (source - target), 256-bit loads.
// 512 blocks x 256 threads. Thread t handles 8-float groups t + k*256
// (k=0..7); every group maps to columns (t*8 .. t*8+7) mod 1024.
// ---------------------------------------------------------------------------
__global__ __launch_bounds__(256)
void mmd_colsum_kernel(const float* __restrict__ src,
                       const float* __restrict__ tgt) {
    const int t   = threadIdx.x;             // 0..255
    const int blk = blockIdx.x;              // 0..511
    const long base = (long)blk * GROUPS_PER_BLK * 8 + t * 8;

    float4 accA = {0.f, 0.f, 0.f, 0.f};
    float4 accB = {0.f, 0.f, 0.f, 0.f};

#pragma unroll
    for (int k = 0; k < 8; k++) {
        const long off = base + (long)k * 256 * 8;
        float4 sa, sb, ta, tb;
        ldg256_keep(src + off, sa, sb);
        ldg256_keep(tgt + off, ta, tb);
        accA.x += sa.x - ta.x;  accA.y += sa.y - ta.y;
        accA.z += sa.z - ta.z;  accA.w += sa.w - ta.w;
        accB.x += sb.x - tb.x;  accB.y += sb.y - tb.y;
        accB.z += sb.z - tb.z;  accB.w += sb.w - tb.w;
    }

    float* dst = &g_partial[blk * GROUPS_PER_BLK + t * 8];
    stg_stream4(dst,     accA);
    stg_stream4(dst + 4, accB);
}

// ---------------------------------------------------------------------------
// Kernel 2: fold 1024 sub-rows (flat mod-1024 columns) -> 32 partial rows.
// 32 blocks x 1024 threads; block b sums sub-rows [b*32, b*32+32).
// ---------------------------------------------------------------------------
__global__ __launch_bounds__(1024)
void mmd_reduce_kernel() {
    const int d = threadIdx.x;               // column 0..1023
    const int b = blockIdx.x;                // 0..31

    float s = 0.f;
#pragma unroll
    for (int r = 0; r < 32; r++) {
        s += g_partial[(long)(b * 32 + r) * D_COLS + d];
    }
    g_partial2[b * D_COLS + d] = s;
}

// ---------------------------------------------------------------------------
// Kernel 3: finish column sums, square, block-reduce, scale, write scalar.
// ---------------------------------------------------------------------------
__global__ __launch_bounds__(1024)
void mmd_final_kernel(float* __restrict__ out) {
    const int d = threadIdx.x;               // column 0..1023

    float s = 0.f;
#pragma unroll
    for (int r = 0; r < 32; r++) {
        s += g_partial2[r * D_COLS + d];
    }
    float sq = s * s;

    __shared__ float red[1024];
    red[d] = sq;
    __syncthreads();
#pragma unroll
    for (int off = 512; off > 0; off >>= 1) {
        if (d < off) red[d] += red[d + off];
        __syncthreads();
    }
    if (d == 0)
        out[0] = red[0] * (1.0f / ((float)N_ROWS * (float)N_ROWS));
}

// ---------------------------------------------------------------------------
extern "C" void kernel_launch(void* const* d_in, const int* in_sizes, int n_in,
                              void* d_out, int out_size) {
    const float* src = (const float*)d_in[0];
    const float* tgt = (const float*)d_in[1];
    float* out = (float*)d_out;

    mmd_colsum_kernel<<<NBLK1, 256>>>(src, tgt);
    mmd_reduce_kernel<<<32, 1024>>>();
    mmd_final_kernel<<<1, 1024>>>(out);
}